// round 12
// baseline (speedup 1.0000x reference)
#include <cuda_runtime.h>
#include <cuda_fp16.h>
#include <math.h>
#include <cstdint>

// Problem constants
#define NN 32
#define TTOT 256
#define VV 25
#define SSUB 3

// ---------------- device scratch -------------------------------------------
__device__ float g_P[(size_t)204800 * 288];          // per row (n,t,u): qa|kb|xd
__device__ float g_M1p[8 * SSUB * NN * VV * VV];
__device__ float g_B[SSUB * NN * VV * VV];

// ---------------- K1: mma.sync fp16-split GEMM -> g_P ----------------------
// X(204800x64) @ [Wa|Wb|Wd](64x288). grid (1600, 3): per CTA M=128, N=96, K=64.
// chunk 0 (qa|kb): 2 passes (Ahi*B + Alo*B), fp32 accum  -- feeds softmax
// chunks 1,2 (xd): 1 pass  (Ahi*B)                        -- linear path
#define AST 72
#define K1_A_ELEMS (128 * AST)
#define K1_B_ELEMS (96 * AST)
#define K1_SMEM_BYTES ((K1_A_ELEMS * 2 + K1_B_ELEMS) * 2 + 96 * 4)

__device__ __forceinline__ void mma16816(float* d, uint32_t a0, uint32_t a1,
                                         uint32_t a2, uint32_t a3,
                                         uint32_t b0, uint32_t b1) {
    asm volatile(
        "mma.sync.aligned.m16n8k16.row.col.f32.f16.f16.f32 "
        "{%0,%1,%2,%3}, {%4,%5,%6,%7}, {%8,%9}, {%0,%1,%2,%3};"
        : "+f"(d[0]), "+f"(d[1]), "+f"(d[2]), "+f"(d[3])
        : "r"(a0), "r"(a1), "r"(a2), "r"(a3), "r"(b0), "r"(b1));
}

__global__ void __launch_bounds__(256) k1_mma(
        const float* __restrict__ x,
        const float* __restrict__ Wa, const float* __restrict__ ba,
        const float* __restrict__ Wb, const float* __restrict__ bb,
        const float* __restrict__ Wd) {
    extern __shared__ char smem[];
    __half* sAhi = (__half*)smem;
    __half* sAlo = sAhi + K1_A_ELEMS;
    __half* sB   = sAlo + K1_A_ELEMS;
    float* sBias = (float*)(sB + K1_B_ELEMS);

    int tid = threadIdx.x;
    int lane = tid & 31, warp = tid >> 5;
    int wm = (warp & 3) * 32;
    int wn = (warp >> 2) * 48;
    int r0 = blockIdx.x * 128;
    int c0 = blockIdx.y * 96;
    int npass = (blockIdx.y == 0) ? 2 : 1;

    {
        const float4* xs = (const float4*)(x + (size_t)r0 * 64);
        for (int idx = tid; idx < 2048; idx += 256) {
            float4 v = xs[idx];
            int row = idx >> 4, c = (idx & 15) * 4;
            __half h0 = __float2half(v.x), h1 = __float2half(v.y);
            __half h2 = __float2half(v.z), h3 = __float2half(v.w);
            __half2 H01 = __halves2half2(h0, h1);
            __half2 H23 = __halves2half2(h2, h3);
            *(uint2*)(sAhi + row * AST + c) = make_uint2(*(uint32_t*)&H01, *(uint32_t*)&H23);
            if (npass == 2) {
                __half l0 = __float2half(v.x - __half2float(h0));
                __half l1 = __float2half(v.y - __half2float(h1));
                __half l2 = __float2half(v.z - __half2float(h2));
                __half l3 = __float2half(v.w - __half2float(h3));
                __half2 L01 = __halves2half2(l0, l1);
                __half2 L23 = __halves2half2(l2, l3);
                *(uint2*)(sAlo + row * AST + c) = make_uint2(*(uint32_t*)&L01, *(uint32_t*)&L23);
            }
        }
    }
    for (int idx = tid; idx < 96 * 64; idx += 256) {
        int nn_ = idx >> 6, k = idx & 63;
        int j = c0 + nn_;
        float v;
        if (j < 48)      { v = Wa[((j >> 4) * 64 + k) * 16 + (j & 15)]; }
        else if (j < 96) { int jj = j - 48; v = Wb[((jj >> 4) * 64 + k) * 16 + (jj & 15)]; }
        else             { int jj = j - 96; v = Wd[((jj >> 6) * 64 + k) * 64 + (jj & 63)]; }
        sB[nn_ * AST + k] = __float2half(v);
    }
    for (int idx = tid; idx < 96; idx += 256) {
        int j = c0 + idx;
        sBias[idx] = (j < 48) ? ba[j] : ((j < 96) ? bb[j - 48] : 0.f);
    }
    __syncthreads();

    float acc[2][6][4];
    #pragma unroll
    for (int mi = 0; mi < 2; mi++)
        #pragma unroll
        for (int nt = 0; nt < 6; nt++)
            #pragma unroll
            for (int q = 0; q < 4; q++) acc[mi][nt][q] = 0.f;

    int ar = lane >> 2;
    int ac = (lane & 3) * 2;

    for (int p = 0; p < npass; p++) {
        const __half* Ap = (p == 0) ? sAhi : sAlo;
        #pragma unroll
        for (int kk = 0; kk < 64; kk += 16) {
            uint32_t af[2][4];
            #pragma unroll
            for (int mi = 0; mi < 2; mi++) {
                const __half* ab = Ap + (wm + mi * 16 + ar) * AST + kk + ac;
                af[mi][0] = *(const uint32_t*)(ab);
                af[mi][1] = *(const uint32_t*)(ab + 8 * AST);
                af[mi][2] = *(const uint32_t*)(ab + 8);
                af[mi][3] = *(const uint32_t*)(ab + 8 * AST + 8);
            }
            #pragma unroll
            for (int nt = 0; nt < 6; nt++) {
                const __half* bb_ = sB + (wn + nt * 8 + ar) * AST + kk + ac;
                uint32_t b0 = *(const uint32_t*)(bb_);
                uint32_t b1 = *(const uint32_t*)(bb_ + 8);
                mma16816(acc[0][nt], af[0][0], af[0][1], af[0][2], af[0][3], b0, b1);
                mma16816(acc[1][nt], af[1][0], af[1][1], af[1][2], af[1][3], b0, b1);
            }
        }
    }

    #pragma unroll
    for (int mi = 0; mi < 2; mi++) {
        int row = r0 + wm + mi * 16 + (lane >> 2);
        #pragma unroll
        for (int nt = 0; nt < 6; nt++) {
            int lc = wn + nt * 8 + (lane & 3) * 2;
            float bx = sBias[lc], by = sBias[lc + 1];
            float* d0 = g_P + (size_t)row * 288 + c0 + lc;
            float* d1 = g_P + (size_t)(row + 8) * 288 + c0 + lc;
            *(float2*)d0 = make_float2(acc[mi][nt][0] + bx, acc[mi][nt][1] + by);
            *(float2*)d1 = make_float2(acc[mi][nt][2] + bx, acc[mi][nt][3] + by);
        }
    }
}

// ---------------- K2: A1 logit partials ------------------------------------
__global__ void __launch_bounds__(256) k2_m1() {
    __shared__ float sqa[VV * 17];
    __shared__ float skb[VV * 17];
    int tid = threadIdx.x;
    int ch = blockIdx.x;
    int s  = blockIdx.y >> 5;
    int n  = blockIdx.y & 31;
    bool active = tid < 169;
    int u0 = (tid / 13) * 2, v0 = (tid % 13) * 2;
    float a00 = 0.f, a01 = 0.f, a10 = 0.f, a11 = 0.f;

    for (int tt = 0; tt < 32; tt++) {
        int t = ch * 32 + tt;
        const float* base = g_P + (size_t)(n * TTOT + t) * VV * 288;
        for (int idx = tid; idx < 800; idx += 256) {
            int which = idx >= 400;
            int rr = idx - which * 400;
            int u = rr >> 4, i = rr & 15;
            float v = base[u * 288 + (which ? 48 : 0) + s * 16 + i];
            if (which) skb[u * 17 + i] = v; else sqa[u * 17 + i] = v;
        }
        __syncthreads();
        if (active) {
            bool u1ok = (u0 + 1 < VV), v1ok = (v0 + 1 < VV);
            #pragma unroll
            for (int i = 0; i < 16; i++) {
                float q0 = sqa[u0 * 17 + i];
                float q1 = u1ok ? sqa[(u0 + 1) * 17 + i] : 0.f;
                float k0 = skb[v0 * 17 + i];
                float k1 = v1ok ? skb[(v0 + 1) * 17 + i] : 0.f;
                a00 += q0 * k0; a01 += q0 * k1; a10 += q1 * k0; a11 += q1 * k1;
            }
        }
        __syncthreads();
    }
    if (active) {
        float* dst = g_M1p + ((ch * SSUB + s) * NN + n) * 625;
        dst[u0 * 25 + v0] = a00;
        if (v0 + 1 < VV) dst[u0 * 25 + v0 + 1] = a01;
        if (u0 + 1 < VV) dst[(u0 + 1) * 25 + v0] = a10;
        if (u0 + 1 < VV && v0 + 1 < VV) dst[(u0 + 1) * 25 + v0 + 1] = a11;
    }
}

// ---------------- K3: B = (w0*A + w1*softmax(PA)) + w2*softmax(M1/64) ------
__global__ void __launch_bounds__(256) k3_b(
        const float* __restrict__ A, const float* __restrict__ PA,
        const float* __restrict__ wA) {
    int tid = threadIdx.x;
    int s = blockIdx.x >> 5, n = blockIdx.x & 31;
    int warp = tid >> 5, lane = tid & 31;
    float w0 = wA[0], w1 = wA[1], w2 = wA[2];
    for (int u = warp; u < VV; u += 8) {
        float pav = (lane < VV) ? PA[(s * VV + u) * VV + lane] : -1e30f;
        float pmx = pav;
        #pragma unroll
        for (int o = 16; o > 0; o >>= 1) pmx = fmaxf(pmx, __shfl_xor_sync(0xffffffffu, pmx, o));
        float pe = (lane < VV) ? __expf(pav - pmx) : 0.f;
        float psum = pe;
        #pragma unroll
        for (int o = 16; o > 0; o >>= 1) psum += __shfl_xor_sync(0xffffffffu, psum, o);

        float val = -1e30f;
        if (lane < VV) {
            float m = 0.f;
            int off = (s * NN + n) * 625 + u * 25 + lane;
            #pragma unroll
            for (int ch = 0; ch < 8; ch++) m += g_M1p[ch * (SSUB * NN * 625) + off];
            val = m * (1.0f / 64.0f);
        }
        float mx = val;
        #pragma unroll
        for (int o = 16; o > 0; o >>= 1) mx = fmaxf(mx, __shfl_xor_sync(0xffffffffu, mx, o));
        float e = (lane < VV) ? __expf(val - mx) : 0.f;
        float ssum = e;
        #pragma unroll
        for (int o = 16; o > 0; o >>= 1) ssum += __shfl_xor_sync(0xffffffffu, ssum, o);

        if (lane < VV)
            g_B[(s * NN + n) * 625 + u * 25 + lane] =
                w0 * A[(s * VV + u) * VV + lane] + w1 * pe / psum + w2 * e / ssum;
    }
}

// ---------------- K4: per (n,t): fused A2-softmax + y + BN + res + relu ----
// Transposed qa/kb (stride 27: gcd(27,32)=1 -> conflict-free lane loads).
// A2 logits computed inside the softmax warp loop (no intermediate phase).
#define OFF_XD  0                        // 25*196 = 4900
#define OFF_QT  4900                     // 3*16*27 = 1296
#define OFF_KT  6196                     // 1296
#define OFF_AIN 7492                     // 3*650 = 1950 (+2)
#define OFF_YP  9444                     // 2*25*64 = 3200
#define OFF_BD  12644
#define OFF_GP  12708
#define OFF_BE  12772
#define K4_SMEM_FLOATS 12836
#define K4_SMEM_BYTES (K4_SMEM_FLOATS * 4)

__global__ void __launch_bounds__(256) k4_main(
        const float* __restrict__ x, const float* __restrict__ bd,
        const float* __restrict__ gamma, const float* __restrict__ beta,
        const float* __restrict__ wA, float* __restrict__ out) {
    extern __shared__ float sm[];
    float* sXd  = sm + OFF_XD;   // [v][196] (xd: 192 used)
    float* sQT  = sm + OFF_QT;   // [s][i][27]
    float* sKT  = sm + OFF_KT;   // [s][i][27]
    float* sAin = sm + OFF_AIN;  // [s][u*26+v]
    float* sYp  = sm + OFF_YP;
    float* sBd  = sm + OFF_BD;
    float* sGp  = sm + OFF_GP;
    float* sBe  = sm + OFF_BE;

    int tid = threadIdx.x;
    int n = blockIdx.x >> 8, t = blockIdx.x & 255;
    float w3 = wA[3];
    int rowbase = (n * TTOT + t) * VV;
    const float4* gp = (const float4*)(g_P + (size_t)rowbase * 288);

    // load: qa/kb scattered transposed (stride 27), xd as float4
    for (int idx = tid; idx < 1800; idx += 256) {
        float4 v = gp[idx];
        int u = idx / 72, jj = (idx % 72) * 4;
        if (jj < 96) {
            int isk = jj >= 48;
            int j2 = jj - isk * 48;
            int s = j2 >> 4, i = j2 & 15;
            float* base = (isk ? sKT : sQT) + s * 432 + i * 27 + u;
            base[0] = v.x; base[27] = v.y; base[54] = v.z; base[81] = v.w;
        } else {
            *(float4*)(sXd + u * 196 + (jj - 96)) = v;
        }
    }
    if (tid < 64) {
        sBd[tid] = bd[tid] + bd[64 + tid] + bd[128 + tid];
        sGp[tid] = gamma[tid] * rsqrtf(1.0f + 1e-5f);
        sBe[tid] = beta[tid];
    }
    __syncthreads();

    // fused A2 logit + softmax + combine: warp per row, lane per v
    {
        int warp = tid >> 5, lane = tid & 31;
        for (int row = warp; row < 75; row += 8) {
            int s = row / 25, u = row - s * 25;
            float logit = -1e30f;
            if (lane < VV) {
                const float* qt = sQT + s * 432 + u;
                const float* kt = sKT + s * 432 + lane;
                float acc = 0.f;
                #pragma unroll
                for (int i = 0; i < 16; i++)
                    acc += qt[i * 27] * kt[i * 27];
                logit = 0.25f * acc;
            }
            float mx = logit;
            #pragma unroll
            for (int o = 16; o > 0; o >>= 1) mx = fmaxf(mx, __shfl_xor_sync(0xffffffffu, mx, o));
            float e = (lane < VV) ? __expf(logit - mx) : 0.f;
            float ssum = e;
            #pragma unroll
            for (int o = 16; o > 0; o >>= 1) ssum += __shfl_xor_sync(0xffffffffu, ssum, o);
            if (lane < VV)
                sAin[s * 650 + u * 26 + lane] =
                    g_B[(s * NN + n) * 625 + u * 25 + lane] + w3 * e / ssum;
        }
    }
    __syncthreads();

    // y[u][o] = sum_{s,v} A_in[s][u][v] * xd[v][s*64+o]; 2-way split, no divides
    {
        int tq = tid >> 7;
        int r128 = tid & 127;
        int og = r128 & 15; int o0 = og * 4;
        int ug = r128 >> 4;
        int nrow = (ug <= 1) ? 4 : 3;
        float acc[4][4];
        #pragma unroll
        for (int r = 0; r < 4; r++)
            #pragma unroll
            for (int q = 0; q < 4; q++) acc[r][q] = 0.f;
        #pragma unroll
        for (int s = 0; s < 3; s++) {
            int vb = tq ? ((s == 0) ? 25 : ((s == 1) ? 13 : 0)) : 0;
            int ve = tq ? 25 : ((s == 0) ? 25 : ((s == 1) ? 13 : 0));
            const float* ainb = sAin + s * 650;
            const float* xdb = sXd + s * 64 + o0;
            for (int v = vb; v < ve; v++) {
                float4 xv = *(const float4*)(xdb + v * 196);
                const float* ain = ainb + v;
                #pragma unroll
                for (int r = 0; r < 4; r++) {
                    if (r < nrow) {
                        float a = ain[(ug + r * 8) * 26];
                        acc[r][0] += a * xv.x; acc[r][1] += a * xv.y;
                        acc[r][2] += a * xv.z; acc[r][3] += a * xv.w;
                    }
                }
            }
        }
        #pragma unroll
        for (int r = 0; r < 4; r++) {
            int u = ug + r * 8;
            if (r < nrow && u < 25) {
                *(float4*)(sYp + (tq * 25 + u) * 64 + o0) =
                    make_float4(acc[r][0], acc[r][1], acc[r][2], acc[r][3]);
            }
        }
    }
    __syncthreads();

    for (int idx = tid; idx < 400; idx += 256) {
        int u = idx >> 4, o = (idx & 15) * 4;
        float4 y0 = *(float4*)(sYp + (u * 64) + o);
        float4 y1 = *(float4*)(sYp + ((25 + u) * 64) + o);
        int gi = (rowbase + u) * 64 + o;
        float4 xg = *(const float4*)(x + gi);
        float4 res;
        res.x = fmaxf((sBd[o+0] + y0.x + y1.x) * sGp[o+0] + sBe[o+0] + xg.x, 0.f);
        res.y = fmaxf((sBd[o+1] + y0.y + y1.y) * sGp[o+1] + sBe[o+1] + xg.y, 0.f);
        res.z = fmaxf((sBd[o+2] + y0.z + y1.z) * sGp[o+2] + sBe[o+2] + xg.z, 0.f);
        res.w = fmaxf((sBd[o+3] + y0.w + y1.w) * sGp[o+3] + sBe[o+3] + xg.w, 0.f);
        *(float4*)(out + gi) = res;
    }
}

// ---------------- launch ---------------------------------------------------
extern "C" void kernel_launch(void* const* d_in, const int* in_sizes, int n_in,
                              void* d_out, int out_size) {
    const float* x     = (const float*)d_in[0];
    const float* A     = (const float*)d_in[1];
    const float* PA    = (const float*)d_in[2];
    const float* wA    = (const float*)d_in[3];
    const float* Wa    = (const float*)d_in[4];
    const float* ba    = (const float*)d_in[5];
    const float* Wb    = (const float*)d_in[6];
    const float* bb    = (const float*)d_in[7];
    const float* Wd    = (const float*)d_in[8];
    const float* bd    = (const float*)d_in[9];
    const float* gamma = (const float*)d_in[10];
    const float* beta  = (const float*)d_in[11];
    float* out = (float*)d_out;

    cudaFuncSetAttribute(k1_mma, cudaFuncAttributeMaxDynamicSharedMemorySize, K1_SMEM_BYTES);
    cudaFuncSetAttribute(k4_main, cudaFuncAttributeMaxDynamicSharedMemorySize, K4_SMEM_BYTES);

    k1_mma<<<dim3(1600, 3), 256, K1_SMEM_BYTES>>>(x, Wa, ba, Wb, bb, Wd);
    k2_m1<<<dim3(8, SSUB * NN), 256>>>();
    k3_b<<<SSUB * NN, 256>>>(A, PA, wA);
    k4_main<<<NN * TTOT, 256, K4_SMEM_BYTES>>>(x, bd, gamma, beta, wA, out);
}

// round 14
// speedup vs baseline: 1.0307x; 1.0307x over previous
#include <cuda_runtime.h>
#include <cuda_fp16.h>
#include <math.h>
#include <cstdint>

// Problem constants
#define NN 32
#define TTOT 256
#define VV 25
#define SSUB 3

// ---------------- device scratch -------------------------------------------
__device__ float g_P[(size_t)204800 * 288];          // per row (n,t,u): qa|kb|xd
__device__ float g_M1p[8 * SSUB * NN * VV * VV];
__device__ float g_B[SSUB * NN * VV * VV];

// ---------------- K1: mma.sync fp16 GEMM -> g_P ----------------------------
// X(204800x64) @ [Wa|Wb|Wd](64x288). grid (1600, 3): per CTA M=128, N=96, K=64.
// Single fp16 pass everywhere (error budget measured: ~3.5e-4 total).
#define AST 72
#define K1_A_ELEMS (128 * AST)
#define K1_B_ELEMS (96 * AST)
#define K1_SMEM_BYTES ((K1_A_ELEMS + K1_B_ELEMS) * 2 + 96 * 4)

__device__ __forceinline__ void mma16816(float* d, uint32_t a0, uint32_t a1,
                                         uint32_t a2, uint32_t a3,
                                         uint32_t b0, uint32_t b1) {
    asm volatile(
        "mma.sync.aligned.m16n8k16.row.col.f32.f16.f16.f32 "
        "{%0,%1,%2,%3}, {%4,%5,%6,%7}, {%8,%9}, {%0,%1,%2,%3};"
        : "+f"(d[0]), "+f"(d[1]), "+f"(d[2]), "+f"(d[3])
        : "r"(a0), "r"(a1), "r"(a2), "r"(a3), "r"(b0), "r"(b1));
}

__global__ void __launch_bounds__(256) k1_mma(
        const float* __restrict__ x,
        const float* __restrict__ Wa, const float* __restrict__ ba,
        const float* __restrict__ Wb, const float* __restrict__ bb,
        const float* __restrict__ Wd) {
    extern __shared__ char smem[];
    __half* sA = (__half*)smem;
    __half* sB = sA + K1_A_ELEMS;
    float* sBias = (float*)(sB + K1_B_ELEMS);

    int tid = threadIdx.x;
    int lane = tid & 31, warp = tid >> 5;
    int wm = (warp & 3) * 32;
    int wn = (warp >> 2) * 48;
    int r0 = blockIdx.x * 128;
    int c0 = blockIdx.y * 96;

    {
        const float4* xs = (const float4*)(x + (size_t)r0 * 64);
        for (int idx = tid; idx < 2048; idx += 256) {
            float4 v = xs[idx];
            int row = idx >> 4, c = (idx & 15) * 4;
            __half2 H01 = __halves2half2(__float2half(v.x), __float2half(v.y));
            __half2 H23 = __halves2half2(__float2half(v.z), __float2half(v.w));
            *(uint2*)(sA + row * AST + c) = make_uint2(*(uint32_t*)&H01, *(uint32_t*)&H23);
        }
    }
    for (int idx = tid; idx < 96 * 64; idx += 256) {
        int nn_ = idx >> 6, k = idx & 63;
        int j = c0 + nn_;
        float v;
        if (j < 48)      { v = Wa[((j >> 4) * 64 + k) * 16 + (j & 15)]; }
        else if (j < 96) { int jj = j - 48; v = Wb[((jj >> 4) * 64 + k) * 16 + (jj & 15)]; }
        else             { int jj = j - 96; v = Wd[((jj >> 6) * 64 + k) * 64 + (jj & 63)]; }
        sB[nn_ * AST + k] = __float2half(v);
    }
    for (int idx = tid; idx < 96; idx += 256) {
        int j = c0 + idx;
        sBias[idx] = (j < 48) ? ba[j] : ((j < 96) ? bb[j - 48] : 0.f);
    }
    __syncthreads();

    float acc[2][6][4];
    #pragma unroll
    for (int mi = 0; mi < 2; mi++)
        #pragma unroll
        for (int nt = 0; nt < 6; nt++)
            #pragma unroll
            for (int q = 0; q < 4; q++) acc[mi][nt][q] = 0.f;

    int ar = lane >> 2;
    int ac = (lane & 3) * 2;

    #pragma unroll
    for (int kk = 0; kk < 64; kk += 16) {
        uint32_t af[2][4];
        #pragma unroll
        for (int mi = 0; mi < 2; mi++) {
            const __half* ab = sA + (wm + mi * 16 + ar) * AST + kk + ac;
            af[mi][0] = *(const uint32_t*)(ab);
            af[mi][1] = *(const uint32_t*)(ab + 8 * AST);
            af[mi][2] = *(const uint32_t*)(ab + 8);
            af[mi][3] = *(const uint32_t*)(ab + 8 * AST + 8);
        }
        #pragma unroll
        for (int nt = 0; nt < 6; nt++) {
            const __half* bb_ = sB + (wn + nt * 8 + ar) * AST + kk + ac;
            uint32_t b0 = *(const uint32_t*)(bb_);
            uint32_t b1 = *(const uint32_t*)(bb_ + 8);
            mma16816(acc[0][nt], af[0][0], af[0][1], af[0][2], af[0][3], b0, b1);
            mma16816(acc[1][nt], af[1][0], af[1][1], af[1][2], af[1][3], b0, b1);
        }
    }

    #pragma unroll
    for (int mi = 0; mi < 2; mi++) {
        int row = r0 + wm + mi * 16 + (lane >> 2);
        #pragma unroll
        for (int nt = 0; nt < 6; nt++) {
            int lc = wn + nt * 8 + (lane & 3) * 2;
            float bx = sBias[lc], by = sBias[lc + 1];
            float* d0 = g_P + (size_t)row * 288 + c0 + lc;
            float* d1 = g_P + (size_t)(row + 8) * 288 + c0 + lc;
            *(float2*)d0 = make_float2(acc[mi][nt][0] + bx, acc[mi][nt][1] + by);
            *(float2*)d1 = make_float2(acc[mi][nt][2] + bx, acc[mi][nt][3] + by);
        }
    }
}

// ---------------- K2: A1 logit partials ------------------------------------
__global__ void __launch_bounds__(256) k2_m1() {
    __shared__ float sqa[VV * 17];
    __shared__ float skb[VV * 17];
    int tid = threadIdx.x;
    int ch = blockIdx.x;
    int s  = blockIdx.y >> 5;
    int n  = blockIdx.y & 31;
    bool active = tid < 169;
    int u0 = (tid / 13) * 2, v0 = (tid % 13) * 2;
    float a00 = 0.f, a01 = 0.f, a10 = 0.f, a11 = 0.f;

    for (int tt = 0; tt < 32; tt++) {
        int t = ch * 32 + tt;
        const float* base = g_P + (size_t)(n * TTOT + t) * VV * 288;
        for (int idx = tid; idx < 800; idx += 256) {
            int which = idx >= 400;
            int rr = idx - which * 400;
            int u = rr >> 4, i = rr & 15;
            float v = base[u * 288 + (which ? 48 : 0) + s * 16 + i];
            if (which) skb[u * 17 + i] = v; else sqa[u * 17 + i] = v;
        }
        __syncthreads();
        if (active) {
            bool u1ok = (u0 + 1 < VV), v1ok = (v0 + 1 < VV);
            #pragma unroll
            for (int i = 0; i < 16; i++) {
                float q0 = sqa[u0 * 17 + i];
                float q1 = u1ok ? sqa[(u0 + 1) * 17 + i] : 0.f;
                float k0 = skb[v0 * 17 + i];
                float k1 = v1ok ? skb[(v0 + 1) * 17 + i] : 0.f;
                a00 += q0 * k0; a01 += q0 * k1; a10 += q1 * k0; a11 += q1 * k1;
            }
        }
        __syncthreads();
    }
    if (active) {
        float* dst = g_M1p + ((ch * SSUB + s) * NN + n) * 625;
        dst[u0 * 25 + v0] = a00;
        if (v0 + 1 < VV) dst[u0 * 25 + v0 + 1] = a01;
        if (u0 + 1 < VV) dst[(u0 + 1) * 25 + v0] = a10;
        if (u0 + 1 < VV && v0 + 1 < VV) dst[(u0 + 1) * 25 + v0 + 1] = a11;
    }
}

// ---------------- K3: B = (w0*A + w1*softmax(PA)) + w2*softmax(M1/64) ------
__global__ void __launch_bounds__(256) k3_b(
        const float* __restrict__ A, const float* __restrict__ PA,
        const float* __restrict__ wA) {
    int tid = threadIdx.x;
    int s = blockIdx.x >> 5, n = blockIdx.x & 31;
    int warp = tid >> 5, lane = tid & 31;
    float w0 = wA[0], w1 = wA[1], w2 = wA[2];
    for (int u = warp; u < VV; u += 8) {
        float pav = (lane < VV) ? PA[(s * VV + u) * VV + lane] : -1e30f;
        float pmx = pav;
        #pragma unroll
        for (int o = 16; o > 0; o >>= 1) pmx = fmaxf(pmx, __shfl_xor_sync(0xffffffffu, pmx, o));
        float pe = (lane < VV) ? __expf(pav - pmx) : 0.f;
        float psum = pe;
        #pragma unroll
        for (int o = 16; o > 0; o >>= 1) psum += __shfl_xor_sync(0xffffffffu, psum, o);

        float val = -1e30f;
        if (lane < VV) {
            float m = 0.f;
            int off = (s * NN + n) * 625 + u * 25 + lane;
            #pragma unroll
            for (int ch = 0; ch < 8; ch++) m += g_M1p[ch * (SSUB * NN * 625) + off];
            val = m * (1.0f / 64.0f);
        }
        float mx = val;
        #pragma unroll
        for (int o = 16; o > 0; o >>= 1) mx = fmaxf(mx, __shfl_xor_sync(0xffffffffu, mx, o));
        float e = (lane < VV) ? __expf(val - mx) : 0.f;
        float ssum = e;
        #pragma unroll
        for (int o = 16; o > 0; o >>= 1) ssum += __shfl_xor_sync(0xffffffffu, ssum, o);

        if (lane < VV)
            g_B[(s * NN + n) * 625 + u * 25 + lane] =
                w0 * A[(s * VV + u) * VV + lane] + w1 * pe / psum + w2 * e / ssum;
    }
}

// ---------------- K4: per (n,t): A2 + A_in + y + BN + residual + relu ------
// (R11 version: transposed qa/kb stride 26, 2x2-tiled A2, measured 231us)
#define OFF_XD  0                        // 25*196 = 4900
#define OFF_QT  4900                     // 3*16*26 = 1248
#define OFF_KT  6148                     // 1248
#define OFF_AIN 7396                     // 3*650 = 1950 (+2)
#define OFF_YP  9348                     // 2*25*64 = 3200
#define OFF_BD  12548
#define OFF_GP  12612
#define OFF_BE  12676
#define K4_SMEM_FLOATS 12740
#define K4_SMEM_BYTES (K4_SMEM_FLOATS * 4)

__global__ void __launch_bounds__(256) k4_main(
        const float* __restrict__ x, const float* __restrict__ bd,
        const float* __restrict__ gamma, const float* __restrict__ beta,
        const float* __restrict__ wA, float* __restrict__ out) {
    extern __shared__ float sm[];
    float* sXd  = sm + OFF_XD;   // [v][196] (xd: 192 used)
    float* sQT  = sm + OFF_QT;   // [s][i][26]
    float* sKT  = sm + OFF_KT;   // [s][i][26]
    float* sAin = sm + OFF_AIN;  // [s][u*26+v]
    float* sYp  = sm + OFF_YP;
    float* sBd  = sm + OFF_BD;
    float* sGp  = sm + OFF_GP;
    float* sBe  = sm + OFF_BE;

    int tid = threadIdx.x;
    int n = blockIdx.x >> 8, t = blockIdx.x & 255;
    float w3 = wA[3];
    int rowbase = (n * TTOT + t) * VV;
    const float4* gp = (const float4*)(g_P + (size_t)rowbase * 288);

    for (int idx = tid; idx < 1800; idx += 256) {
        float4 v = gp[idx];
        int u = idx / 72, jj = (idx % 72) * 4;
        if (jj < 96) {
            int isk = jj >= 48;
            int j2 = jj - isk * 48;
            int s = j2 >> 4, i = j2 & 15;
            float* base = (isk ? sKT : sQT) + s * 416 + i * 26 + u;
            base[0] = v.x; base[26] = v.y; base[52] = v.z; base[78] = v.w;
        } else {
            *(float4*)(sXd + u * 196 + (jj - 96)) = v;
        }
    }
    if (tid < 64) {
        sBd[tid] = bd[tid] + bd[64 + tid] + bd[128 + tid];
        sGp[tid] = gamma[tid] * rsqrtf(1.0f + 1e-5f);
        sBe[tid] = beta[tid];
    }
    __syncthreads();

    // A2 logits, 2x2 register tiles via transposed float2 loads (scale 1/4)
    if (tid < 169) {
        int u0 = (tid / 13) * 2, v0 = (tid % 13) * 2;
        bool u1 = (u0 + 1 < VV), v1 = (v0 + 1 < VV);
        #pragma unroll
        for (int s = 0; s < 3; s++) {
            const float* qt = sQT + s * 416 + u0;
            const float* kt = sKT + s * 416 + v0;
            float a00 = 0.f, a01 = 0.f, a10 = 0.f, a11 = 0.f;
            #pragma unroll
            for (int i = 0; i < 16; i++) {
                float2 q = *(const float2*)(qt + i * 26);
                float2 k = *(const float2*)(kt + i * 26);
                a00 += q.x * k.x; a01 += q.x * k.y;
                a10 += q.y * k.x; a11 += q.y * k.y;
            }
            float* dst = sAin + s * 650;
            dst[u0 * 26 + v0] = 0.25f * a00;
            if (v1) dst[u0 * 26 + v0 + 1] = 0.25f * a01;
            if (u1) dst[(u0 + 1) * 26 + v0] = 0.25f * a10;
            if (u1 && v1) dst[(u0 + 1) * 26 + v0 + 1] = 0.25f * a11;
        }
    }
    __syncthreads();

    // softmax rows + combine A_in = g_B + w3*softmax(A2); g_B direct (L2-hot)
    {
        int warp = tid >> 5, lane = tid & 31;
        for (int row = warp; row < 75; row += 8) {
            int s = row / 25, u = row - s * 25;
            float val = (lane < VV) ? sAin[s * 650 + u * 26 + lane] : -1e30f;
            float mx = val;
            #pragma unroll
            for (int o = 16; o > 0; o >>= 1) mx = fmaxf(mx, __shfl_xor_sync(0xffffffffu, mx, o));
            float e = (lane < VV) ? __expf(val - mx) : 0.f;
            float ssum = e;
            #pragma unroll
            for (int o = 16; o > 0; o >>= 1) ssum += __shfl_xor_sync(0xffffffffu, ssum, o);
            if (lane < VV)
                sAin[s * 650 + u * 26 + lane] =
                    g_B[(s * NN + n) * 625 + u * 25 + lane] + w3 * e / ssum;
        }
    }
    __syncthreads();

    // y[u][o] = sum_{s,v} A_in[s][u][v] * xd[v][s*64+o]; 2-way split over sv
    {
        int tq = tid >> 7;
        int r128 = tid & 127;
        int og = r128 & 15; int o0 = og * 4;
        int ug = r128 >> 4;
        int sv0 = tq * 38;
        int sv1 = tq ? 75 : 38;
        int nrow = (ug <= 1) ? 4 : 3;
        float acc[4][4];
        #pragma unroll
        for (int r = 0; r < 4; r++)
            #pragma unroll
            for (int q = 0; q < 4; q++) acc[r][q] = 0.f;
        for (int sv = sv0; sv < sv1; sv++) {
            int s = sv / 25, v = sv - s * 25;
            float4 xv = *(const float4*)(sXd + v * 196 + s * 64 + o0);
            const float* ain = sAin + s * 650 + v;
            #pragma unroll
            for (int r = 0; r < 4; r++) {
                if (r < nrow) {
                    float a = ain[(ug + r * 8) * 26];
                    acc[r][0] += a * xv.x; acc[r][1] += a * xv.y;
                    acc[r][2] += a * xv.z; acc[r][3] += a * xv.w;
                }
            }
        }
        #pragma unroll
        for (int r = 0; r < 4; r++) {
            int u = ug + r * 8;
            if (r < nrow && u < 25) {
                *(float4*)(sYp + (tq * 25 + u) * 64 + o0) =
                    make_float4(acc[r][0], acc[r][1], acc[r][2], acc[r][3]);
            }
        }
    }
    __syncthreads();

    for (int idx = tid; idx < 400; idx += 256) {
        int u = idx >> 4, o = (idx & 15) * 4;
        float4 y0 = *(float4*)(sYp + (u * 64) + o);
        float4 y1 = *(float4*)(sYp + ((25 + u) * 64) + o);
        int gi = (rowbase + u) * 64 + o;
        float4 xg = *(const float4*)(x + gi);
        float4 res;
        res.x = fmaxf((sBd[o+0] + y0.x + y1.x) * sGp[o+0] + sBe[o+0] + xg.x, 0.f);
        res.y = fmaxf((sBd[o+1] + y0.y + y1.y) * sGp[o+1] + sBe[o+1] + xg.y, 0.f);
        res.z = fmaxf((sBd[o+2] + y0.z + y1.z) * sGp[o+2] + sBe[o+2] + xg.z, 0.f);
        res.w = fmaxf((sBd[o+3] + y0.w + y1.w) * sGp[o+3] + sBe[o+3] + xg.w, 0.f);
        *(float4*)(out + gi) = res;
    }
}

// ---------------- launch ---------------------------------------------------
extern "C" void kernel_launch(void* const* d_in, const int* in_sizes, int n_in,
                              void* d_out, int out_size) {
    const float* x     = (const float*)d_in[0];
    const float* A     = (const float*)d_in[1];
    const float* PA    = (const float*)d_in[2];
    const float* wA    = (const float*)d_in[3];
    const float* Wa    = (const float*)d_in[4];
    const float* ba    = (const float*)d_in[5];
    const float* Wb    = (const float*)d_in[6];
    const float* bb    = (const float*)d_in[7];
    const float* Wd    = (const float*)d_in[8];
    const float* bd    = (const float*)d_in[9];
    const float* gamma = (const float*)d_in[10];
    const float* beta  = (const float*)d_in[11];
    float* out = (float*)d_out;

    cudaFuncSetAttribute(k1_mma, cudaFuncAttributeMaxDynamicSharedMemorySize, K1_SMEM_BYTES);
    cudaFuncSetAttribute(k4_main, cudaFuncAttributeMaxDynamicSharedMemorySize, K4_SMEM_BYTES);

    k1_mma<<<dim3(1600, 3), 256, K1_SMEM_BYTES>>>(x, Wa, ba, Wb, bb, Wd);
    k2_m1<<<dim3(8, SSUB * NN), 256>>>();
    k3_b<<<SSUB * NN, 256>>>(A, PA, wA);
    k4_main<<<NN * TTOT, 256, K4_SMEM_BYTES>>>(x, bd, gamma, beta, wA, out);
}

// round 15
// speedup vs baseline: 1.0744x; 1.0424x over previous
#include <cuda_runtime.h>
#include <cuda_fp16.h>
#include <math.h>
#include <cstdint>

// Problem constants
#define NN 32
#define TTOT 256
#define VV 25
#define SSUB 3

// ---------------- device scratch -------------------------------------------
__device__ __half g_P[(size_t)204800 * 288];         // per row (n,t,u): qa|kb|xd (fp16)
__device__ float g_M1p[8 * SSUB * NN * VV * VV];
__device__ float g_B[SSUB * NN * VV * VV];

// ---------------- K1: mma.sync fp16 GEMM -> g_P (fp16) ---------------------
// X(204800x64) @ [Wa|Wb|Wd](64x288). grid (1600, 3): per CTA M=128, N=96, K=64.
#define AST 72
#define K1_A_ELEMS (128 * AST)
#define K1_B_ELEMS (96 * AST)
#define K1_SMEM_BYTES ((K1_A_ELEMS + K1_B_ELEMS) * 2 + 96 * 4)

__device__ __forceinline__ void mma16816(float* d, uint32_t a0, uint32_t a1,
                                         uint32_t a2, uint32_t a3,
                                         uint32_t b0, uint32_t b1) {
    asm volatile(
        "mma.sync.aligned.m16n8k16.row.col.f32.f16.f16.f32 "
        "{%0,%1,%2,%3}, {%4,%5,%6,%7}, {%8,%9}, {%0,%1,%2,%3};"
        : "+f"(d[0]), "+f"(d[1]), "+f"(d[2]), "+f"(d[3])
        : "r"(a0), "r"(a1), "r"(a2), "r"(a3), "r"(b0), "r"(b1));
}

__global__ void __launch_bounds__(256) k1_mma(
        const float* __restrict__ x,
        const float* __restrict__ Wa, const float* __restrict__ ba,
        const float* __restrict__ Wb, const float* __restrict__ bb,
        const float* __restrict__ Wd) {
    extern __shared__ char smem[];
    __half* sA = (__half*)smem;
    __half* sB = sA + K1_A_ELEMS;
    float* sBias = (float*)(sB + K1_B_ELEMS);

    int tid = threadIdx.x;
    int lane = tid & 31, warp = tid >> 5;
    int wm = (warp & 3) * 32;
    int wn = (warp >> 2) * 48;
    int r0 = blockIdx.x * 128;
    int c0 = blockIdx.y * 96;

    {
        const float4* xs = (const float4*)(x + (size_t)r0 * 64);
        for (int idx = tid; idx < 2048; idx += 256) {
            float4 v = xs[idx];
            int row = idx >> 4, c = (idx & 15) * 4;
            __half2 H01 = __halves2half2(__float2half(v.x), __float2half(v.y));
            __half2 H23 = __halves2half2(__float2half(v.z), __float2half(v.w));
            *(uint2*)(sA + row * AST + c) = make_uint2(*(uint32_t*)&H01, *(uint32_t*)&H23);
        }
    }
    for (int idx = tid; idx < 96 * 64; idx += 256) {
        int nn_ = idx >> 6, k = idx & 63;
        int j = c0 + nn_;
        float v;
        if (j < 48)      { v = Wa[((j >> 4) * 64 + k) * 16 + (j & 15)]; }
        else if (j < 96) { int jj = j - 48; v = Wb[((jj >> 4) * 64 + k) * 16 + (jj & 15)]; }
        else             { int jj = j - 96; v = Wd[((jj >> 6) * 64 + k) * 64 + (jj & 63)]; }
        sB[nn_ * AST + k] = __float2half(v);
    }
    for (int idx = tid; idx < 96; idx += 256) {
        int j = c0 + idx;
        sBias[idx] = (j < 48) ? ba[j] : ((j < 96) ? bb[j - 48] : 0.f);
    }
    __syncthreads();

    float acc[2][6][4];
    #pragma unroll
    for (int mi = 0; mi < 2; mi++)
        #pragma unroll
        for (int nt = 0; nt < 6; nt++)
            #pragma unroll
            for (int q = 0; q < 4; q++) acc[mi][nt][q] = 0.f;

    int ar = lane >> 2;
    int ac = (lane & 3) * 2;

    #pragma unroll
    for (int kk = 0; kk < 64; kk += 16) {
        uint32_t af[2][4];
        #pragma unroll
        for (int mi = 0; mi < 2; mi++) {
            const __half* ab = sA + (wm + mi * 16 + ar) * AST + kk + ac;
            af[mi][0] = *(const uint32_t*)(ab);
            af[mi][1] = *(const uint32_t*)(ab + 8 * AST);
            af[mi][2] = *(const uint32_t*)(ab + 8);
            af[mi][3] = *(const uint32_t*)(ab + 8 * AST + 8);
        }
        #pragma unroll
        for (int nt = 0; nt < 6; nt++) {
            const __half* bb_ = sB + (wn + nt * 8 + ar) * AST + kk + ac;
            uint32_t b0 = *(const uint32_t*)(bb_);
            uint32_t b1 = *(const uint32_t*)(bb_ + 8);
            mma16816(acc[0][nt], af[0][0], af[0][1], af[0][2], af[0][3], b0, b1);
            mma16816(acc[1][nt], af[1][0], af[1][1], af[1][2], af[1][3], b0, b1);
        }
    }

    #pragma unroll
    for (int mi = 0; mi < 2; mi++) {
        int row = r0 + wm + mi * 16 + (lane >> 2);
        #pragma unroll
        for (int nt = 0; nt < 6; nt++) {
            int lc = wn + nt * 8 + (lane & 3) * 2;
            float bx = sBias[lc], by = sBias[lc + 1];
            __half2 h0 = __halves2half2(__float2half(acc[mi][nt][0] + bx),
                                        __float2half(acc[mi][nt][1] + by));
            __half2 h1 = __halves2half2(__float2half(acc[mi][nt][2] + bx),
                                        __float2half(acc[mi][nt][3] + by));
            *(uint32_t*)(g_P + (size_t)row * 288 + c0 + lc) = *(uint32_t*)&h0;
            *(uint32_t*)(g_P + (size_t)(row + 8) * 288 + c0 + lc) = *(uint32_t*)&h1;
        }
    }
}

// ---------------- K2: A1 logit partials ------------------------------------
__global__ void __launch_bounds__(256) k2_m1() {
    __shared__ float sqa[VV * 17];
    __shared__ float skb[VV * 17];
    int tid = threadIdx.x;
    int ch = blockIdx.x;
    int s  = blockIdx.y >> 5;
    int n  = blockIdx.y & 31;
    bool active = tid < 169;
    int u0 = (tid / 13) * 2, v0 = (tid % 13) * 2;
    float a00 = 0.f, a01 = 0.f, a10 = 0.f, a11 = 0.f;

    for (int tt = 0; tt < 32; tt++) {
        int t = ch * 32 + tt;
        const __half* base = g_P + (size_t)(n * TTOT + t) * VV * 288;
        for (int idx = tid; idx < 800; idx += 256) {
            int which = idx >= 400;
            int rr = idx - which * 400;
            int u = rr >> 4, i = rr & 15;
            float v = __half2float(base[u * 288 + (which ? 48 : 0) + s * 16 + i]);
            if (which) skb[u * 17 + i] = v; else sqa[u * 17 + i] = v;
        }
        __syncthreads();
        if (active) {
            bool u1ok = (u0 + 1 < VV), v1ok = (v0 + 1 < VV);
            #pragma unroll
            for (int i = 0; i < 16; i++) {
                float q0 = sqa[u0 * 17 + i];
                float q1 = u1ok ? sqa[(u0 + 1) * 17 + i] : 0.f;
                float k0 = skb[v0 * 17 + i];
                float k1 = v1ok ? skb[(v0 + 1) * 17 + i] : 0.f;
                a00 += q0 * k0; a01 += q0 * k1; a10 += q1 * k0; a11 += q1 * k1;
            }
        }
        __syncthreads();
    }
    if (active) {
        float* dst = g_M1p + ((ch * SSUB + s) * NN + n) * 625;
        dst[u0 * 25 + v0] = a00;
        if (v0 + 1 < VV) dst[u0 * 25 + v0 + 1] = a01;
        if (u0 + 1 < VV) dst[(u0 + 1) * 25 + v0] = a10;
        if (u0 + 1 < VV && v0 + 1 < VV) dst[(u0 + 1) * 25 + v0 + 1] = a11;
    }
}

// ---------------- K3: B = (w0*A + w1*softmax(PA)) + w2*softmax(M1/64) ------
__global__ void __launch_bounds__(256) k3_b(
        const float* __restrict__ A, const float* __restrict__ PA,
        const float* __restrict__ wA) {
    int tid = threadIdx.x;
    int s = blockIdx.x >> 5, n = blockIdx.x & 31;
    int warp = tid >> 5, lane = tid & 31;
    float w0 = wA[0], w1 = wA[1], w2 = wA[2];
    for (int u = warp; u < VV; u += 8) {
        float pav = (lane < VV) ? PA[(s * VV + u) * VV + lane] : -1e30f;
        float pmx = pav;
        #pragma unroll
        for (int o = 16; o > 0; o >>= 1) pmx = fmaxf(pmx, __shfl_xor_sync(0xffffffffu, pmx, o));
        float pe = (lane < VV) ? __expf(pav - pmx) : 0.f;
        float psum = pe;
        #pragma unroll
        for (int o = 16; o > 0; o >>= 1) psum += __shfl_xor_sync(0xffffffffu, psum, o);

        float val = -1e30f;
        if (lane < VV) {
            float m = 0.f;
            int off = (s * NN + n) * 625 + u * 25 + lane;
            #pragma unroll
            for (int ch = 0; ch < 8; ch++) m += g_M1p[ch * (SSUB * NN * 625) + off];
            val = m * (1.0f / 64.0f);
        }
        float mx = val;
        #pragma unroll
        for (int o = 16; o > 0; o >>= 1) mx = fmaxf(mx, __shfl_xor_sync(0xffffffffu, mx, o));
        float e = (lane < VV) ? __expf(val - mx) : 0.f;
        float ssum = e;
        #pragma unroll
        for (int o = 16; o > 0; o >>= 1) ssum += __shfl_xor_sync(0xffffffffu, ssum, o);

        if (lane < VV)
            g_B[(s * NN + n) * 625 + u * 25 + lane] =
                w0 * A[(s * VV + u) * VV + lane] + w1 * pe / psum + w2 * e / ssum;
    }
}

// ---------------- K4: per (n,t): A2 + softmax + y(BN+res+relu fused) -------
// fp16 g_P loads; o-split y phase (no sYp staging, no reduce barrier).
#define OFF_XD  0                        // 25*196 = 4900
#define OFF_QT  4900                     // 3*16*26 = 1248
#define OFF_KT  6148                     // 1248
#define OFF_AIN 7396                     // 3*650 = 1950 (+2)
#define OFF_BD  9348
#define OFF_GP  9412
#define OFF_BE  9476
#define K4_SMEM_FLOATS 9540
#define K4_SMEM_BYTES (K4_SMEM_FLOATS * 4)

__global__ void __launch_bounds__(256) k4_main(
        const float* __restrict__ x, const float* __restrict__ bd,
        const float* __restrict__ gamma, const float* __restrict__ beta,
        const float* __restrict__ wA, float* __restrict__ out) {
    extern __shared__ float sm[];
    float* sXd  = sm + OFF_XD;   // [v][196] (xd: 192 used)
    float* sQT  = sm + OFF_QT;   // [s][i][26]
    float* sKT  = sm + OFF_KT;   // [s][i][26]
    float* sAin = sm + OFF_AIN;  // [s][u*26+v]
    float* sBd  = sm + OFF_BD;
    float* sGp  = sm + OFF_GP;
    float* sBe  = sm + OFF_BE;

    int tid = threadIdx.x;
    int n = blockIdx.x >> 8, t = blockIdx.x & 255;
    float w3 = wA[3];
    int rowbase = (n * TTOT + t) * VV;
    const __half* gp = g_P + (size_t)rowbase * 288;

    // load 7200 halves as 900 uint4 (8 halves each); convert to fp32 smem
    for (int idx = tid; idx < 900; idx += 256) {
        uint4 raw = *(const uint4*)(gp + idx * 8);
        __half2 h0 = *(__half2*)&raw.x, h1 = *(__half2*)&raw.y;
        __half2 h2 = *(__half2*)&raw.z, h3 = *(__half2*)&raw.w;
        float f[8];
        f[0] = __half2float(h0.x); f[1] = __half2float(h0.y);
        f[2] = __half2float(h1.x); f[3] = __half2float(h1.y);
        f[4] = __half2float(h2.x); f[5] = __half2float(h2.y);
        f[6] = __half2float(h3.x); f[7] = __half2float(h3.y);
        int u = idx / 36, jj = (idx % 36) * 8;
        if (jj < 96) {
            int isk = jj >= 48;
            int j2 = jj - isk * 48;
            int s = j2 >> 4, i0 = j2 & 15;
            float* base = (isk ? sKT : sQT) + s * 416 + i0 * 26 + u;
            #pragma unroll
            for (int k = 0; k < 8; k++) base[k * 26] = f[k];
        } else {
            float* dst = sXd + u * 196 + (jj - 96);
            *(float4*)(dst) = make_float4(f[0], f[1], f[2], f[3]);
            *(float4*)(dst + 4) = make_float4(f[4], f[5], f[6], f[7]);
        }
    }
    if (tid < 64) {
        sBd[tid] = bd[tid] + bd[64 + tid] + bd[128 + tid];
        sGp[tid] = gamma[tid] * rsqrtf(1.0f + 1e-5f);
        sBe[tid] = beta[tid];
    }
    __syncthreads();

    // A2 logits, 2x2 register tiles via transposed float2 loads (scale 1/4)
    if (tid < 169) {
        int u0 = (tid / 13) * 2, v0 = (tid % 13) * 2;
        bool u1 = (u0 + 1 < VV), v1 = (v0 + 1 < VV);
        #pragma unroll
        for (int s = 0; s < 3; s++) {
            const float* qt = sQT + s * 416 + u0;
            const float* kt = sKT + s * 416 + v0;
            float a00 = 0.f, a01 = 0.f, a10 = 0.f, a11 = 0.f;
            #pragma unroll
            for (int i = 0; i < 16; i++) {
                float2 q = *(const float2*)(qt + i * 26);
                float2 k = *(const float2*)(kt + i * 26);
                a00 += q.x * k.x; a01 += q.x * k.y;
                a10 += q.y * k.x; a11 += q.y * k.y;
            }
            float* dst = sAin + s * 650;
            dst[u0 * 26 + v0] = 0.25f * a00;
            if (v1) dst[u0 * 26 + v0 + 1] = 0.25f * a01;
            if (u1) dst[(u0 + 1) * 26 + v0] = 0.25f * a10;
            if (u1 && v1) dst[(u0 + 1) * 26 + v0 + 1] = 0.25f * a11;
        }
    }
    __syncthreads();

    // softmax rows + combine A_in = g_B + w3*softmax(A2)
    {
        int warp = tid >> 5, lane = tid & 31;
        for (int row = warp; row < 75; row += 8) {
            int s = row / 25, u = row - s * 25;
            float val = (lane < VV) ? sAin[s * 650 + u * 26 + lane] : -1e30f;
            float mx = val;
            #pragma unroll
            for (int o = 16; o > 0; o >>= 1) mx = fmaxf(mx, __shfl_xor_sync(0xffffffffu, mx, o));
            float e = (lane < VV) ? __expf(val - mx) : 0.f;
            float ssum = e;
            #pragma unroll
            for (int o = 16; o > 0; o >>= 1) ssum += __shfl_xor_sync(0xffffffffu, ssum, o);
            if (lane < VV)
                sAin[s * 650 + u * 26 + lane] =
                    g_B[(s * NN + n) * 625 + u * 25 + lane] + w3 * e / ssum;
        }
    }
    __syncthreads();

    // y: o-split. thread (og 0..15, ug 0..15) -> rows {ug, ug+16}, cols o0..o0+3.
    // full 75-sv accumulation, fused BN + residual + relu + store.
    {
        int og = tid & 15; int o0 = og * 4;
        int ug = tid >> 4;                 // 0..15
        bool row2 = (ug < 9);              // ug+16 < 25
        float acc0[4] = {0.f, 0.f, 0.f, 0.f};
        float acc1[4] = {0.f, 0.f, 0.f, 0.f};
        #pragma unroll
        for (int s = 0; s < 3; s++) {
            const float* a0p = sAin + s * 650 + ug * 26;
            const float* a1p = sAin + s * 650 + (ug + 16) * 26;
            const float* xdb = sXd + s * 64 + o0;
            #pragma unroll 5
            for (int v = 0; v < 25; v++) {
                float4 xv = *(const float4*)(xdb + v * 196);
                float a0 = a0p[v];
                acc0[0] += a0 * xv.x; acc0[1] += a0 * xv.y;
                acc0[2] += a0 * xv.z; acc0[3] += a0 * xv.w;
                if (row2) {
                    float a1 = a1p[v];
                    acc1[0] += a1 * xv.x; acc1[1] += a1 * xv.y;
                    acc1[2] += a1 * xv.z; acc1[3] += a1 * xv.w;
                }
            }
        }
        #pragma unroll
        for (int r = 0; r < 2; r++) {
            int u = ug + r * 16;
            if (r == 1 && !row2) break;
            float* ac = (r == 0) ? acc0 : acc1;
            int gi = (rowbase + u) * 64 + o0;
            float4 xg = *(const float4*)(x + gi);
            float4 res;
            res.x = fmaxf((sBd[o0+0] + ac[0]) * sGp[o0+0] + sBe[o0+0] + xg.x, 0.f);
            res.y = fmaxf((sBd[o0+1] + ac[1]) * sGp[o0+1] + sBe[o0+1] + xg.y, 0.f);
            res.z = fmaxf((sBd[o0+2] + ac[2]) * sGp[o0+2] + sBe[o0+2] + xg.z, 0.f);
            res.w = fmaxf((sBd[o0+3] + ac[3]) * sGp[o0+3] + sBe[o0+3] + xg.w, 0.f);
            *(float4*)(out + gi) = res;
        }
    }
}

// ---------------- launch ---------------------------------------------------
extern "C" void kernel_launch(void* const* d_in, const int* in_sizes, int n_in,
                              void* d_out, int out_size) {
    const float* x     = (const float*)d_in[0];
    const float* A     = (const float*)d_in[1];
    const float* PA    = (const float*)d_in[2];
    const float* wA    = (const float*)d_in[3];
    const float* Wa    = (const float*)d_in[4];
    const float* ba    = (const float*)d_in[5];
    const float* Wb    = (const float*)d_in[6];
    const float* bb    = (const float*)d_in[7];
    const float* Wd    = (const float*)d_in[8];
    const float* bd    = (const float*)d_in[9];
    const float* gamma = (const float*)d_in[10];
    const float* beta  = (const float*)d_in[11];
    float* out = (float*)d_out;

    cudaFuncSetAttribute(k1_mma, cudaFuncAttributeMaxDynamicSharedMemorySize, K1_SMEM_BYTES);
    cudaFuncSetAttribute(k4_main, cudaFuncAttributeMaxDynamicSharedMemorySize, K4_SMEM_BYTES);

    k1_mma<<<dim3(1600, 3), 256, K1_SMEM_BYTES>>>(x, Wa, ba, Wb, bb, Wd);
    k2_m1<<<dim3(8, SSUB * NN), 256>>>();
    k3_b<<<SSUB * NN, 256>>>(A, PA, wA);
    k4_main<<<NN * TTOT, 256, K4_SMEM_BYTES>>>(x, bd, gamma, beta, wA, out);
}

// round 16
// speedup vs baseline: 1.2364x; 1.1508x over previous
#include <cuda_runtime.h>
#include <cuda_fp16.h>
#include <math.h>
#include <cstdint>

// Problem constants
#define NN 32
#define TTOT 256
#define VV 25
#define SSUB 3

// ---------------- device scratch -------------------------------------------
__device__ __half g_P[(size_t)204800 * 288];         // per row (n,t,u): qa|kb|xd (fp16)
__device__ float g_M1p[8 * SSUB * NN * VV * VV];
__device__ float g_B[SSUB * NN * VV * VV];

// ---------------- K1: mma.sync fp16 GEMM -> g_P (fp16) ---------------------
#define AST 72
#define K1_A_ELEMS (128 * AST)
#define K1_B_ELEMS (96 * AST)
#define K1_SMEM_BYTES ((K1_A_ELEMS + K1_B_ELEMS) * 2 + 96 * 4)

__device__ __forceinline__ void mma16816(float* d, uint32_t a0, uint32_t a1,
                                         uint32_t a2, uint32_t a3,
                                         uint32_t b0, uint32_t b1) {
    asm volatile(
        "mma.sync.aligned.m16n8k16.row.col.f32.f16.f16.f32 "
        "{%0,%1,%2,%3}, {%4,%5,%6,%7}, {%8,%9}, {%0,%1,%2,%3};"
        : "+f"(d[0]), "+f"(d[1]), "+f"(d[2]), "+f"(d[3])
        : "r"(a0), "r"(a1), "r"(a2), "r"(a3), "r"(b0), "r"(b1));
}

__global__ void __launch_bounds__(256) k1_mma(
        const float* __restrict__ x,
        const float* __restrict__ Wa, const float* __restrict__ ba,
        const float* __restrict__ Wb, const float* __restrict__ bb,
        const float* __restrict__ Wd) {
    extern __shared__ char smem[];
    __half* sA = (__half*)smem;
    __half* sB = sA + K1_A_ELEMS;
    float* sBias = (float*)(sB + K1_B_ELEMS);

    int tid = threadIdx.x;
    int lane = tid & 31, warp = tid >> 5;
    int wm = (warp & 3) * 32;
    int wn = (warp >> 2) * 48;
    int r0 = blockIdx.x * 128;
    int c0 = blockIdx.y * 96;

    {
        const float4* xs = (const float4*)(x + (size_t)r0 * 64);
        for (int idx = tid; idx < 2048; idx += 256) {
            float4 v = xs[idx];
            int row = idx >> 4, c = (idx & 15) * 4;
            __half2 H01 = __halves2half2(__float2half(v.x), __float2half(v.y));
            __half2 H23 = __halves2half2(__float2half(v.z), __float2half(v.w));
            *(uint2*)(sA + row * AST + c) = make_uint2(*(uint32_t*)&H01, *(uint32_t*)&H23);
        }
    }
    for (int idx = tid; idx < 96 * 64; idx += 256) {
        int nn_ = idx >> 6, k = idx & 63;
        int j = c0 + nn_;
        float v;
        if (j < 48)      { v = Wa[((j >> 4) * 64 + k) * 16 + (j & 15)]; }
        else if (j < 96) { int jj = j - 48; v = Wb[((jj >> 4) * 64 + k) * 16 + (jj & 15)]; }
        else             { int jj = j - 96; v = Wd[((jj >> 6) * 64 + k) * 64 + (jj & 63)]; }
        sB[nn_ * AST + k] = __float2half(v);
    }
    for (int idx = tid; idx < 96; idx += 256) {
        int j = c0 + idx;
        sBias[idx] = (j < 48) ? ba[j] : ((j < 96) ? bb[j - 48] : 0.f);
    }
    __syncthreads();

    float acc[2][6][4];
    #pragma unroll
    for (int mi = 0; mi < 2; mi++)
        #pragma unroll
        for (int nt = 0; nt < 6; nt++)
            #pragma unroll
            for (int q = 0; q < 4; q++) acc[mi][nt][q] = 0.f;

    int ar = lane >> 2;
    int ac = (lane & 3) * 2;

    #pragma unroll
    for (int kk = 0; kk < 64; kk += 16) {
        uint32_t af[2][4];
        #pragma unroll
        for (int mi = 0; mi < 2; mi++) {
            const __half* ab = sA + (wm + mi * 16 + ar) * AST + kk + ac;
            af[mi][0] = *(const uint32_t*)(ab);
            af[mi][1] = *(const uint32_t*)(ab + 8 * AST);
            af[mi][2] = *(const uint32_t*)(ab + 8);
            af[mi][3] = *(const uint32_t*)(ab + 8 * AST + 8);
        }
        #pragma unroll
        for (int nt = 0; nt < 6; nt++) {
            const __half* bb_ = sB + (wn + nt * 8 + ar) * AST + kk + ac;
            uint32_t b0 = *(const uint32_t*)(bb_);
            uint32_t b1 = *(const uint32_t*)(bb_ + 8);
            mma16816(acc[0][nt], af[0][0], af[0][1], af[0][2], af[0][3], b0, b1);
            mma16816(acc[1][nt], af[1][0], af[1][1], af[1][2], af[1][3], b0, b1);
        }
    }

    #pragma unroll
    for (int mi = 0; mi < 2; mi++) {
        int row = r0 + wm + mi * 16 + (lane >> 2);
        #pragma unroll
        for (int nt = 0; nt < 6; nt++) {
            int lc = wn + nt * 8 + (lane & 3) * 2;
            float bx = sBias[lc], by = sBias[lc + 1];
            __half2 h0 = __halves2half2(__float2half(acc[mi][nt][0] + bx),
                                        __float2half(acc[mi][nt][1] + by));
            __half2 h1 = __halves2half2(__float2half(acc[mi][nt][2] + bx),
                                        __float2half(acc[mi][nt][3] + by));
            *(uint32_t*)(g_P + (size_t)row * 288 + c0 + lc) = *(uint32_t*)&h0;
            *(uint32_t*)(g_P + (size_t)(row + 8) * 288 + c0 + lc) = *(uint32_t*)&h1;
        }
    }
}

// ---------------- K2: A1 logit partials ------------------------------------
__global__ void __launch_bounds__(256) k2_m1() {
    __shared__ float sqa[VV * 17];
    __shared__ float skb[VV * 17];
    int tid = threadIdx.x;
    int ch = blockIdx.x;
    int s  = blockIdx.y >> 5;
    int n  = blockIdx.y & 31;
    bool active = tid < 169;
    int u0 = (tid / 13) * 2, v0 = (tid % 13) * 2;
    float a00 = 0.f, a01 = 0.f, a10 = 0.f, a11 = 0.f;

    for (int tt = 0; tt < 32; tt++) {
        int t = ch * 32 + tt;
        const __half* base = g_P + (size_t)(n * TTOT + t) * VV * 288;
        for (int idx = tid; idx < 800; idx += 256) {
            int which = idx >= 400;
            int rr = idx - which * 400;
            int u = rr >> 4, i = rr & 15;
            float v = __half2float(base[u * 288 + (which ? 48 : 0) + s * 16 + i]);
            if (which) skb[u * 17 + i] = v; else sqa[u * 17 + i] = v;
        }
        __syncthreads();
        if (active) {
            bool u1ok = (u0 + 1 < VV), v1ok = (v0 + 1 < VV);
            #pragma unroll
            for (int i = 0; i < 16; i++) {
                float q0 = sqa[u0 * 17 + i];
                float q1 = u1ok ? sqa[(u0 + 1) * 17 + i] : 0.f;
                float k0 = skb[v0 * 17 + i];
                float k1 = v1ok ? skb[(v0 + 1) * 17 + i] : 0.f;
                a00 += q0 * k0; a01 += q0 * k1; a10 += q1 * k0; a11 += q1 * k1;
            }
        }
        __syncthreads();
    }
    if (active) {
        float* dst = g_M1p + ((ch * SSUB + s) * NN + n) * 625;
        dst[u0 * 25 + v0] = a00;
        if (v0 + 1 < VV) dst[u0 * 25 + v0 + 1] = a01;
        if (u0 + 1 < VV) dst[(u0 + 1) * 25 + v0] = a10;
        if (u0 + 1 < VV && v0 + 1 < VV) dst[(u0 + 1) * 25 + v0 + 1] = a11;
    }
}

// ---------------- K3: B = (w0*A + w1*softmax(PA)) + w2*softmax(M1/64) ------
__global__ void __launch_bounds__(256) k3_b(
        const float* __restrict__ A, const float* __restrict__ PA,
        const float* __restrict__ wA) {
    int tid = threadIdx.x;
    int s = blockIdx.x >> 5, n = blockIdx.x & 31;
    int warp = tid >> 5, lane = tid & 31;
    float w0 = wA[0], w1 = wA[1], w2 = wA[2];
    for (int u = warp; u < VV; u += 8) {
        float pav = (lane < VV) ? PA[(s * VV + u) * VV + lane] : -1e30f;
        float pmx = pav;
        #pragma unroll
        for (int o = 16; o > 0; o >>= 1) pmx = fmaxf(pmx, __shfl_xor_sync(0xffffffffu, pmx, o));
        float pe = (lane < VV) ? __expf(pav - pmx) : 0.f;
        float psum = pe;
        #pragma unroll
        for (int o = 16; o > 0; o >>= 1) psum += __shfl_xor_sync(0xffffffffu, psum, o);

        float val = -1e30f;
        if (lane < VV) {
            float m = 0.f;
            int off = (s * NN + n) * 625 + u * 25 + lane;
            #pragma unroll
            for (int ch = 0; ch < 8; ch++) m += g_M1p[ch * (SSUB * NN * 625) + off];
            val = m * (1.0f / 64.0f);
        }
        float mx = val;
        #pragma unroll
        for (int o = 16; o > 0; o >>= 1) mx = fmaxf(mx, __shfl_xor_sync(0xffffffffu, mx, o));
        float e = (lane < VV) ? __expf(val - mx) : 0.f;
        float ssum = e;
        #pragma unroll
        for (int o = 16; o > 0; o >>= 1) ssum += __shfl_xor_sync(0xffffffffu, ssum, o);

        if (lane < VV)
            g_B[(s * NN + n) * 625 + u * 25 + lane] =
                w0 * A[(s * VV + u) * VV + lane] + w1 * pe / psum + w2 * e / ssum;
    }
}

// ---------------- K4: fp16 smem staging (halved LDS bytes) -----------------
// byte offsets: sXdH 0 (25*200 halves = 10000B), sQTH 10000 (2496B),
// sKTH 12496 (2496B), floats at 15008: sAin 1952, sBd/gp/be 192.
#define OFFB_XD  0
#define OFFB_QT  10000
#define OFFB_KT  12496
#define OFFB_F   15008
#define OFF_AIN  0
#define OFF_BD   1952
#define OFF_GP   2016
#define OFF_BE   2080
#define K4_SMEM_BYTES (OFFB_F + 2144 * 4)

__global__ void __launch_bounds__(256) k4_main(
        const float* __restrict__ x, const float* __restrict__ bd,
        const float* __restrict__ gamma, const float* __restrict__ beta,
        const float* __restrict__ wA, float* __restrict__ out) {
    extern __shared__ char smraw[];
    __half* sXdH = (__half*)(smraw + OFFB_XD);   // [v][200]
    __half* sQTH = (__half*)(smraw + OFFB_QT);   // [s][i][26]
    __half* sKTH = (__half*)(smraw + OFFB_KT);   // [s][i][26]
    float* smf  = (float*)(smraw + OFFB_F);
    float* sAin = smf + OFF_AIN;                 // [s][u*26+v]
    float* sBd  = smf + OFF_BD;
    float* sGp  = smf + OFF_GP;
    float* sBe  = smf + OFF_BE;

    int tid = threadIdx.x;
    int n = blockIdx.x >> 8, t = blockIdx.x & 255;
    float w3 = wA[3];
    int rowbase = (n * TTOT + t) * VV;
    const __half* gp = g_P + (size_t)rowbase * 288;

    // load 7200 halves as 900 uint4 (8 halves each); keep fp16 in smem
    for (int idx = tid; idx < 900; idx += 256) {
        uint4 raw = *(const uint4*)(gp + idx * 8);
        int u = idx / 36, jj = (idx % 36) * 8;
        if (jj < 96) {
            int isk = jj >= 48;
            int j2 = jj - isk * 48;
            int s = j2 >> 4, i0 = j2 & 15;
            __half* base = (isk ? sKTH : sQTH) + s * 416 + i0 * 26 + u;
            __half2 h0 = *(__half2*)&raw.x, h1 = *(__half2*)&raw.y;
            __half2 h2 = *(__half2*)&raw.z, h3 = *(__half2*)&raw.w;
            base[0 * 26] = h0.x; base[1 * 26] = h0.y;
            base[2 * 26] = h1.x; base[3 * 26] = h1.y;
            base[4 * 26] = h2.x; base[5 * 26] = h2.y;
            base[6 * 26] = h3.x; base[7 * 26] = h3.y;
        } else {
            *(uint4*)(sXdH + u * 200 + (jj - 96)) = raw;
        }
    }
    if (tid < 64) {
        sBd[tid] = bd[tid] + bd[64 + tid] + bd[128 + tid];
        sGp[tid] = gamma[tid] * rsqrtf(1.0f + 1e-5f);
        sBe[tid] = beta[tid];
    }
    __syncthreads();

    // A2 logits, 2x2 register tiles via half2 loads (scale 1/4)
    if (tid < 169) {
        int u0 = (tid / 13) * 2, v0 = (tid % 13) * 2;
        bool u1 = (u0 + 1 < VV), v1 = (v0 + 1 < VV);
        #pragma unroll
        for (int s = 0; s < 3; s++) {
            const __half* qt = sQTH + s * 416 + u0;
            const __half* kt = sKTH + s * 416 + v0;
            float a00 = 0.f, a01 = 0.f, a10 = 0.f, a11 = 0.f;
            #pragma unroll
            for (int i = 0; i < 16; i++) {
                __half2 qh = *(const __half2*)(qt + i * 26);
                __half2 kh = *(const __half2*)(kt + i * 26);
                float qx = __half2float(qh.x), qy = __half2float(qh.y);
                float kx = __half2float(kh.x), ky = __half2float(kh.y);
                a00 += qx * kx; a01 += qx * ky;
                a10 += qy * kx; a11 += qy * ky;
            }
            float* dst = sAin + s * 650;
            dst[u0 * 26 + v0] = 0.25f * a00;
            if (v1) dst[u0 * 26 + v0 + 1] = 0.25f * a01;
            if (u1) dst[(u0 + 1) * 26 + v0] = 0.25f * a10;
            if (u1 && v1) dst[(u0 + 1) * 26 + v0 + 1] = 0.25f * a11;
        }
    }
    __syncthreads();

    // softmax rows + combine A_in = g_B + w3*softmax(A2)
    {
        int warp = tid >> 5, lane = tid & 31;
        for (int row = warp; row < 75; row += 8) {
            int s = row / 25, u = row - s * 25;
            float val = (lane < VV) ? sAin[s * 650 + u * 26 + lane] : -1e30f;
            float mx = val;
            #pragma unroll
            for (int o = 16; o > 0; o >>= 1) mx = fmaxf(mx, __shfl_xor_sync(0xffffffffu, mx, o));
            float e = (lane < VV) ? __expf(val - mx) : 0.f;
            float ssum = e;
            #pragma unroll
            for (int o = 16; o > 0; o >>= 1) ssum += __shfl_xor_sync(0xffffffffu, ssum, o);
            if (lane < VV)
                sAin[s * 650 + u * 26 + lane] =
                    g_B[(s * NN + n) * 625 + u * 25 + lane] + w3 * e / ssum;
        }
    }
    __syncthreads();

    // y: o-split; xv via 8B fp16 loads; fused BN + residual + relu + store
    {
        int og = tid & 15; int o0 = og * 4;
        int ug = tid >> 4;
        bool row2 = (ug < 9);
        float acc0[4] = {0.f, 0.f, 0.f, 0.f};
        float acc1[4] = {0.f, 0.f, 0.f, 0.f};
        #pragma unroll
        for (int s = 0; s < 3; s++) {
            const float* a0p = sAin + s * 650 + ug * 26;
            const float* a1p = sAin + s * 650 + (ug + 16) * 26;
            const __half* xdb = sXdH + s * 64 + o0;
            #pragma unroll 5
            for (int v = 0; v < 25; v++) {
                uint2 rawv = *(const uint2*)(xdb + v * 200);
                __half2 hx = *(__half2*)&rawv.x, hy = *(__half2*)&rawv.y;
                float x0 = __half2float(hx.x), x1 = __half2float(hx.y);
                float x2 = __half2float(hy.x), x3 = __half2float(hy.y);
                float a0 = a0p[v];
                acc0[0] += a0 * x0; acc0[1] += a0 * x1;
                acc0[2] += a0 * x2; acc0[3] += a0 * x3;
                if (row2) {
                    float a1 = a1p[v];
                    acc1[0] += a1 * x0; acc1[1] += a1 * x1;
                    acc1[2] += a1 * x2; acc1[3] += a1 * x3;
                }
            }
        }
        #pragma unroll
        for (int r = 0; r < 2; r++) {
            int u = ug + r * 16;
            if (r == 1 && !row2) break;
            float* ac = (r == 0) ? acc0 : acc1;
            int gi = (rowbase + u) * 64 + o0;
            float4 xg = *(const float4*)(x + gi);
            float4 res;
            res.x = fmaxf((sBd[o0+0] + ac[0]) * sGp[o0+0] + sBe[o0+0] + xg.x, 0.f);
            res.y = fmaxf((sBd[o0+1] + ac[1]) * sGp[o0+1] + sBe[o0+1] + xg.y, 0.f);
            res.z = fmaxf((sBd[o0+2] + ac[2]) * sGp[o0+2] + sBe[o0+2] + xg.z, 0.f);
            res.w = fmaxf((sBd[o0+3] + ac[3]) * sGp[o0+3] + sBe[o0+3] + xg.w, 0.f);
            *(float4*)(out + gi) = res;
        }
    }
}

// ---------------- launch ---------------------------------------------------
extern "C" void kernel_launch(void* const* d_in, const int* in_sizes, int n_in,
                              void* d_out, int out_size) {
    const float* x     = (const float*)d_in[0];
    const float* A     = (const float*)d_in[1];
    const float* PA    = (const float*)d_in[2];
    const float* wA    = (const float*)d_in[3];
    const float* Wa    = (const float*)d_in[4];
    const float* ba    = (const float*)d_in[5];
    const float* Wb    = (const float*)d_in[6];
    const float* bb    = (const float*)d_in[7];
    const float* Wd    = (const float*)d_in[8];
    const float* bd    = (const float*)d_in[9];
    const float* gamma = (const float*)d_in[10];
    const float* beta  = (const float*)d_in[11];
    float* out = (float*)d_out;

    cudaFuncSetAttribute(k1_mma, cudaFuncAttributeMaxDynamicSharedMemorySize, K1_SMEM_BYTES);
    cudaFuncSetAttribute(k4_main, cudaFuncAttributeMaxDynamicSharedMemorySize, K4_SMEM_BYTES);

    k1_mma<<<dim3(1600, 3), 256, K1_SMEM_BYTES>>>(x, Wa, ba, Wb, bb, Wd);
    k2_m1<<<dim3(8, SSUB * NN), 256>>>();
    k3_b<<<SSUB * NN, 256>>>(A, PA, wA);
    k4_main<<<NN * TTOT, 256, K4_SMEM_BYTES>>>(x, bd, gamma, beta, wA, out);
}

// round 17
// speedup vs baseline: 1.2993x; 1.0509x over previous
#include <cuda_runtime.h>
#include <cuda_fp16.h>
#include <math.h>
#include <cstdint>

// Problem constants
#define NN 32
#define TTOT 256
#define VV 25
#define SSUB 3

// ---------------- device scratch -------------------------------------------
__device__ __half g_P[(size_t)204800 * 288];         // per row (n,t,u): qa|kb|xd (fp16)
__device__ float g_M1p[8 * SSUB * NN * VV * VV];
__device__ float g_B[SSUB * NN * VV * VV];

// ---------------- K1: mma.sync fp16 GEMM -> g_P (fp16) ---------------------
// X(204800x64) @ [Wa|Wb|Wd](64x288). grid 1600: per CTA M=128, N=288 (3 chunks
// of 96 processed sequentially; A loaded/converted ONCE -> x read 1x not 3x).
#define AST 72
#define K1_A_ELEMS (128 * AST)
#define K1_B_ELEMS (96 * AST)
#define K1_SMEM_BYTES ((K1_A_ELEMS + K1_B_ELEMS) * 2 + 96 * 4)

__device__ __forceinline__ void mma16816(float* d, uint32_t a0, uint32_t a1,
                                         uint32_t a2, uint32_t a3,
                                         uint32_t b0, uint32_t b1) {
    asm volatile(
        "mma.sync.aligned.m16n8k16.row.col.f32.f16.f16.f32 "
        "{%0,%1,%2,%3}, {%4,%5,%6,%7}, {%8,%9}, {%0,%1,%2,%3};"
        : "+f"(d[0]), "+f"(d[1]), "+f"(d[2]), "+f"(d[3])
        : "r"(a0), "r"(a1), "r"(a2), "r"(a3), "r"(b0), "r"(b1));
}

__global__ void __launch_bounds__(256) k1_mma(
        const float* __restrict__ x,
        const float* __restrict__ Wa, const float* __restrict__ ba,
        const float* __restrict__ Wb, const float* __restrict__ bb,
        const float* __restrict__ Wd) {
    extern __shared__ char smem[];
    __half* sA = (__half*)smem;
    __half* sB = sA + K1_A_ELEMS;
    float* sBias = (float*)(sB + K1_B_ELEMS);

    int tid = threadIdx.x;
    int lane = tid & 31, warp = tid >> 5;
    int wm = (warp & 3) * 32;
    int wn = (warp >> 2) * 48;
    int r0 = blockIdx.x * 128;

    // ---- A tile loaded & converted ONCE -----------------------------------
    {
        const float4* xs = (const float4*)(x + (size_t)r0 * 64);
        for (int idx = tid; idx < 2048; idx += 256) {
            float4 v = xs[idx];
            int row = idx >> 4, c = (idx & 15) * 4;
            __half2 H01 = __halves2half2(__float2half(v.x), __float2half(v.y));
            __half2 H23 = __halves2half2(__float2half(v.z), __float2half(v.w));
            *(uint2*)(sA + row * AST + c) = make_uint2(*(uint32_t*)&H01, *(uint32_t*)&H23);
        }
    }

    int ar = lane >> 2;
    int ac = (lane & 3) * 2;

    for (int cc = 0; cc < 3; cc++) {
        int c0 = cc * 96;
        __syncthreads();   // A ready (cc=0) / prior MMA done reading sB
        for (int idx = tid; idx < 96 * 64; idx += 256) {
            int nn_ = idx >> 6, k = idx & 63;
            int j = c0 + nn_;
            float v;
            if (j < 48)      { v = Wa[((j >> 4) * 64 + k) * 16 + (j & 15)]; }
            else if (j < 96) { int jj = j - 48; v = Wb[((jj >> 4) * 64 + k) * 16 + (jj & 15)]; }
            else             { int jj = j - 96; v = Wd[((jj >> 6) * 64 + k) * 64 + (jj & 63)]; }
            sB[nn_ * AST + k] = __float2half(v);
        }
        for (int idx = tid; idx < 96; idx += 256) {
            int j = c0 + idx;
            sBias[idx] = (j < 48) ? ba[j] : ((j < 96) ? bb[j - 48] : 0.f);
        }
        __syncthreads();

        float acc[2][6][4];
        #pragma unroll
        for (int mi = 0; mi < 2; mi++)
            #pragma unroll
            for (int nt = 0; nt < 6; nt++)
                #pragma unroll
                for (int q = 0; q < 4; q++) acc[mi][nt][q] = 0.f;

        #pragma unroll
        for (int kk = 0; kk < 64; kk += 16) {
            uint32_t af[2][4];
            #pragma unroll
            for (int mi = 0; mi < 2; mi++) {
                const __half* ab = sA + (wm + mi * 16 + ar) * AST + kk + ac;
                af[mi][0] = *(const uint32_t*)(ab);
                af[mi][1] = *(const uint32_t*)(ab + 8 * AST);
                af[mi][2] = *(const uint32_t*)(ab + 8);
                af[mi][3] = *(const uint32_t*)(ab + 8 * AST + 8);
            }
            #pragma unroll
            for (int nt = 0; nt < 6; nt++) {
                const __half* bb_ = sB + (wn + nt * 8 + ar) * AST + kk + ac;
                uint32_t b0 = *(const uint32_t*)(bb_);
                uint32_t b1 = *(const uint32_t*)(bb_ + 8);
                mma16816(acc[0][nt], af[0][0], af[0][1], af[0][2], af[0][3], b0, b1);
                mma16816(acc[1][nt], af[1][0], af[1][1], af[1][2], af[1][3], b0, b1);
            }
        }

        #pragma unroll
        for (int mi = 0; mi < 2; mi++) {
            int row = r0 + wm + mi * 16 + (lane >> 2);
            #pragma unroll
            for (int nt = 0; nt < 6; nt++) {
                int lc = wn + nt * 8 + (lane & 3) * 2;
                float bx = sBias[lc], by = sBias[lc + 1];
                __half2 h0 = __halves2half2(__float2half(acc[mi][nt][0] + bx),
                                            __float2half(acc[mi][nt][1] + by));
                __half2 h1 = __halves2half2(__float2half(acc[mi][nt][2] + bx),
                                            __float2half(acc[mi][nt][3] + by));
                *(uint32_t*)(g_P + (size_t)row * 288 + c0 + lc) = *(uint32_t*)&h0;
                *(uint32_t*)(g_P + (size_t)(row + 8) * 288 + c0 + lc) = *(uint32_t*)&h1;
            }
        }
    }
}

// ---------------- K2: A1 logit partials (t batched 8-wide) -----------------
__global__ void __launch_bounds__(256) k2_m1() {
    __shared__ float sqa[8][VV * 17];
    __shared__ float skb[8][VV * 17];
    int tid = threadIdx.x;
    int ch = blockIdx.x;
    int s  = blockIdx.y >> 5;
    int n  = blockIdx.y & 31;
    bool active = tid < 169;
    int u0 = (tid / 13) * 2, v0 = (tid % 13) * 2;
    float a00 = 0.f, a01 = 0.f, a10 = 0.f, a11 = 0.f;

    for (int it = 0; it < 4; it++) {
        int tbase = ch * 32 + it * 8;
        for (int idx = tid; idx < 6400; idx += 256) {
            int j = idx / 800, rr = idx - j * 800;
            int which = rr >= 400;
            int r2 = rr - which * 400;
            int u = r2 >> 4, i = r2 & 15;
            const __half* base = g_P + (size_t)(n * TTOT + tbase + j) * VV * 288;
            float v = __half2float(base[u * 288 + (which ? 48 : 0) + s * 16 + i]);
            if (which) skb[j][u * 17 + i] = v; else sqa[j][u * 17 + i] = v;
        }
        __syncthreads();
        if (active) {
            bool u1ok = (u0 + 1 < VV), v1ok = (v0 + 1 < VV);
            #pragma unroll 2
            for (int j = 0; j < 8; j++) {
                #pragma unroll
                for (int i = 0; i < 16; i++) {
                    float q0 = sqa[j][u0 * 17 + i];
                    float q1 = u1ok ? sqa[j][(u0 + 1) * 17 + i] : 0.f;
                    float k0 = skb[j][v0 * 17 + i];
                    float k1 = v1ok ? skb[j][(v0 + 1) * 17 + i] : 0.f;
                    a00 += q0 * k0; a01 += q0 * k1; a10 += q1 * k0; a11 += q1 * k1;
                }
            }
        }
        __syncthreads();
    }
    if (active) {
        float* dst = g_M1p + ((ch * SSUB + s) * NN + n) * 625;
        dst[u0 * 25 + v0] = a00;
        if (v0 + 1 < VV) dst[u0 * 25 + v0 + 1] = a01;
        if (u0 + 1 < VV) dst[(u0 + 1) * 25 + v0] = a10;
        if (u0 + 1 < VV && v0 + 1 < VV) dst[(u0 + 1) * 25 + v0 + 1] = a11;
    }
}

// ---------------- K3: B = (w0*A + w1*softmax(PA)) + w2*softmax(M1/64) ------
__global__ void __launch_bounds__(256) k3_b(
        const float* __restrict__ A, const float* __restrict__ PA,
        const float* __restrict__ wA) {
    int tid = threadIdx.x;
    int s = blockIdx.x >> 5, n = blockIdx.x & 31;
    int warp = tid >> 5, lane = tid & 31;
    float w0 = wA[0], w1 = wA[1], w2 = wA[2];
    for (int u = warp; u < VV; u += 8) {
        float pav = (lane < VV) ? PA[(s * VV + u) * VV + lane] : -1e30f;
        float pmx = pav;
        #pragma unroll
        for (int o = 16; o > 0; o >>= 1) pmx = fmaxf(pmx, __shfl_xor_sync(0xffffffffu, pmx, o));
        float pe = (lane < VV) ? __expf(pav - pmx) : 0.f;
        float psum = pe;
        #pragma unroll
        for (int o = 16; o > 0; o >>= 1) psum += __shfl_xor_sync(0xffffffffu, psum, o);

        float val = -1e30f;
        if (lane < VV) {
            float m = 0.f;
            int off = (s * NN + n) * 625 + u * 25 + lane;
            #pragma unroll
            for (int ch = 0; ch < 8; ch++) m += g_M1p[ch * (SSUB * NN * 625) + off];
            val = m * (1.0f / 64.0f);
        }
        float mx = val;
        #pragma unroll
        for (int o = 16; o > 0; o >>= 1) mx = fmaxf(mx, __shfl_xor_sync(0xffffffffu, mx, o));
        float e = (lane < VV) ? __expf(val - mx) : 0.f;
        float ssum = e;
        #pragma unroll
        for (int o = 16; o > 0; o >>= 1) ssum += __shfl_xor_sync(0xffffffffu, ssum, o);

        if (lane < VV)
            g_B[(s * NN + n) * 625 + u * 25 + lane] =
                w0 * A[(s * VV + u) * VV + lane] + w1 * pe / psum + w2 * e / ssum;
    }
}

// ---------------- K4: fp16 smem staging (R16, 164us) -----------------------
#define OFFB_XD  0
#define OFFB_QT  10000
#define OFFB_KT  12496
#define OFFB_F   15008
#define OFF_AIN  0
#define OFF_BD   1952
#define OFF_GP   2016
#define OFF_BE   2080
#define K4_SMEM_BYTES (OFFB_F + 2144 * 4)

__global__ void __launch_bounds__(256) k4_main(
        const float* __restrict__ x, const float* __restrict__ bd,
        const float* __restrict__ gamma, const float* __restrict__ beta,
        const float* __restrict__ wA, float* __restrict__ out) {
    extern __shared__ char smraw[];
    __half* sXdH = (__half*)(smraw + OFFB_XD);   // [v][200]
    __half* sQTH = (__half*)(smraw + OFFB_QT);   // [s][i][26]
    __half* sKTH = (__half*)(smraw + OFFB_KT);   // [s][i][26]
    float* smf  = (float*)(smraw + OFFB_F);
    float* sAin = smf + OFF_AIN;                 // [s][u*26+v]
    float* sBd  = smf + OFF_BD;
    float* sGp  = smf + OFF_GP;
    float* sBe  = smf + OFF_BE;

    int tid = threadIdx.x;
    int n = blockIdx.x >> 8, t = blockIdx.x & 255;
    float w3 = wA[3];
    int rowbase = (n * TTOT + t) * VV;
    const __half* gp = g_P + (size_t)rowbase * 288;

    for (int idx = tid; idx < 900; idx += 256) {
        uint4 raw = *(const uint4*)(gp + idx * 8);
        int u = idx / 36, jj = (idx % 36) * 8;
        if (jj < 96) {
            int isk = jj >= 48;
            int j2 = jj - isk * 48;
            int s = j2 >> 4, i0 = j2 & 15;
            __half* base = (isk ? sKTH : sQTH) + s * 416 + i0 * 26 + u;
            __half2 h0 = *(__half2*)&raw.x, h1 = *(__half2*)&raw.y;
            __half2 h2 = *(__half2*)&raw.z, h3 = *(__half2*)&raw.w;
            base[0 * 26] = h0.x; base[1 * 26] = h0.y;
            base[2 * 26] = h1.x; base[3 * 26] = h1.y;
            base[4 * 26] = h2.x; base[5 * 26] = h2.y;
            base[6 * 26] = h3.x; base[7 * 26] = h3.y;
        } else {
            *(uint4*)(sXdH + u * 200 + (jj - 96)) = raw;
        }
    }
    if (tid < 64) {
        sBd[tid] = bd[tid] + bd[64 + tid] + bd[128 + tid];
        sGp[tid] = gamma[tid] * rsqrtf(1.0f + 1e-5f);
        sBe[tid] = beta[tid];
    }
    __syncthreads();

    if (tid < 169) {
        int u0 = (tid / 13) * 2, v0 = (tid % 13) * 2;
        bool u1 = (u0 + 1 < VV), v1 = (v0 + 1 < VV);
        #pragma unroll
        for (int s = 0; s < 3; s++) {
            const __half* qt = sQTH + s * 416 + u0;
            const __half* kt = sKTH + s * 416 + v0;
            float a00 = 0.f, a01 = 0.f, a10 = 0.f, a11 = 0.f;
            #pragma unroll
            for (int i = 0; i < 16; i++) {
                __half2 qh = *(const __half2*)(qt + i * 26);
                __half2 kh = *(const __half2*)(kt + i * 26);
                float qx = __half2float(qh.x), qy = __half2float(qh.y);
                float kx = __half2float(kh.x), ky = __half2float(kh.y);
                a00 += qx * kx; a01 += qx * ky;
                a10 += qy * kx; a11 += qy * ky;
            }
            float* dst = sAin + s * 650;
            dst[u0 * 26 + v0] = 0.25f * a00;
            if (v1) dst[u0 * 26 + v0 + 1] = 0.25f * a01;
            if (u1) dst[(u0 + 1) * 26 + v0] = 0.25f * a10;
            if (u1 && v1) dst[(u0 + 1) * 26 + v0 + 1] = 0.25f * a11;
        }
    }
    __syncthreads();

    {
        int warp = tid >> 5, lane = tid & 31;
        for (int row = warp; row < 75; row += 8) {
            int s = row / 25, u = row - s * 25;
            float val = (lane < VV) ? sAin[s * 650 + u * 26 + lane] : -1e30f;
            float mx = val;
            #pragma unroll
            for (int o = 16; o > 0; o >>= 1) mx = fmaxf(mx, __shfl_xor_sync(0xffffffffu, mx, o));
            float e = (lane < VV) ? __expf(val - mx) : 0.f;
            float ssum = e;
            #pragma unroll
            for (int o = 16; o > 0; o >>= 1) ssum += __shfl_xor_sync(0xffffffffu, ssum, o);
            if (lane < VV)
                sAin[s * 650 + u * 26 + lane] =
                    g_B[(s * NN + n) * 625 + u * 25 + lane] + w3 * e / ssum;
        }
    }
    __syncthreads();

    {
        int og = tid & 15; int o0 = og * 4;
        int ug = tid >> 4;
        bool row2 = (ug < 9);
        float acc0[4] = {0.f, 0.f, 0.f, 0.f};
        float acc1[4] = {0.f, 0.f, 0.f, 0.f};
        #pragma unroll
        for (int s = 0; s < 3; s++) {
            const float* a0p = sAin + s * 650 + ug * 26;
            const float* a1p = sAin + s * 650 + (ug + 16) * 26;
            const __half* xdb = sXdH + s * 64 + o0;
            #pragma unroll 5
            for (int v = 0; v < 25; v++) {
                uint2 rawv = *(const uint2*)(xdb + v * 200);
                __half2 hx = *(__half2*)&rawv.x, hy = *(__half2*)&rawv.y;
                float x0 = __half2float(hx.x), x1 = __half2float(hx.y);
                float x2 = __half2float(hy.x), x3 = __half2float(hy.y);
                float a0 = a0p[v];
                acc0[0] += a0 * x0; acc0[1] += a0 * x1;
                acc0[2] += a0 * x2; acc0[3] += a0 * x3;
                if (row2) {
                    float a1 = a1p[v];
                    acc1[0] += a1 * x0; acc1[1] += a1 * x1;
                    acc1[2] += a1 * x2; acc1[3] += a1 * x3;
                }
            }
        }
        #pragma unroll
        for (int r = 0; r < 2; r++) {
            int u = ug + r * 16;
            if (r == 1 && !row2) break;
            float* ac = (r == 0) ? acc0 : acc1;
            int gi = (rowbase + u) * 64 + o0;
            float4 xg = *(const float4*)(x + gi);
            float4 res;
            res.x = fmaxf((sBd[o0+0] + ac[0]) * sGp[o0+0] + sBe[o0+0] + xg.x, 0.f);
            res.y = fmaxf((sBd[o0+1] + ac[1]) * sGp[o0+1] + sBe[o0+1] + xg.y, 0.f);
            res.z = fmaxf((sBd[o0+2] + ac[2]) * sGp[o0+2] + sBe[o0+2] + xg.z, 0.f);
            res.w = fmaxf((sBd[o0+3] + ac[3]) * sGp[o0+3] + sBe[o0+3] + xg.w, 0.f);
            *(float4*)(out + gi) = res;
        }
    }
}

// ---------------- launch ---------------------------------------------------
extern "C" void kernel_launch(void* const* d_in, const int* in_sizes, int n_in,
                              void* d_out, int out_size) {
    const float* x     = (const float*)d_in[0];
    const float* A     = (const float*)d_in[1];
    const float* PA    = (const float*)d_in[2];
    const float* wA    = (const float*)d_in[3];
    const float* Wa    = (const float*)d_in[4];
    const float* ba    = (const float*)d_in[5];
    const float* Wb    = (const float*)d_in[6];
    const float* bb    = (const float*)d_in[7];
    const float* Wd    = (const float*)d_in[8];
    const float* bd    = (const float*)d_in[9];
    const float* gamma = (const float*)d_in[10];
    const float* beta  = (const float*)d_in[11];
    float* out = (float*)d_out;

    cudaFuncSetAttribute(k1_mma, cudaFuncAttributeMaxDynamicSharedMemorySize, K1_SMEM_BYTES);
    cudaFuncSetAttribute(k4_main, cudaFuncAttributeMaxDynamicSharedMemorySize, K4_SMEM_BYTES);

    k1_mma<<<1600, 256, K1_SMEM_BYTES>>>(x, Wa, ba, Wb, bb, Wd);
    k2_m1<<<dim3(8, SSUB * NN), 256>>>();
    k3_b<<<SSUB * NN, 256>>>(A, PA, wA);
    k4_main<<<NN * TTOT, 256, K4_SMEM_BYTES>>>(x, bd, gamma, beta, wA, out);
}